// round 1
// baseline (speedup 1.0000x reference)
#include <cuda_runtime.h>
#include <cuda_bf16.h>
#include <cstdint>

// Problem constants
#define BB 4
#define LT 1024
#define LS 1024
#define DD 1024
#define HH 16
#define HD 64
#define FF 4096
#define MTOT (BB*LT)   // 4096 rows

// ---------------------------------------------------------------------------
// Scratch: one big __device__ array (no allocations allowed).
// Layout (floats):
//   h    : 4M  (normed activations)
//   q    : 4M  (query projection)
//   attn : 4M  (attention output, pre out-proj)
//   x1   : 4M  (attn_x residual)
//   x2   : 4M  (cross_x residual)
//   ffn  : 16M (FFN hidden)
#define SLOT (MTOT*DD)                     // 4M floats
__device__ float g_scratch[5*SLOT + MTOT*FF];

// ---------------------------------------------------------------------------
// RMSNorm: one block per row of 1024 floats, 256 threads * float4
__global__ void rmsnorm_kernel(const float* __restrict__ x,
                               const float* __restrict__ g,
                               float* __restrict__ out)
{
    __shared__ float red[256];
    int row = blockIdx.x;
    int tid = threadIdx.x;
    const float4* xr = (const float4*)(x + (size_t)row * DD);
    float4 v = xr[tid];
    float ss = v.x*v.x + v.y*v.y + v.z*v.z + v.w*v.w;
    red[tid] = ss;
    __syncthreads();
    #pragma unroll
    for (int s = 128; s > 0; s >>= 1) {
        if (tid < s) red[tid] += red[tid + s];
        __syncthreads();
    }
    float inv = rsqrtf(red[0] * (1.0f/(float)DD) + 1e-6f);
    const float4 gg = ((const float4*)g)[tid];
    float4 o;
    o.x = v.x * inv * gg.x;
    o.y = v.y * inv * gg.y;
    o.z = v.z * inv * gg.z;
    o.w = v.w * inv * gg.w;
    ((float4*)(out + (size_t)row * DD))[tid] = o;
}

// ---------------------------------------------------------------------------
// SGEMM: C[M,N] = A[M,K] @ B[K,N], row-major, fp32.
// 128x128 block tile, BK=16, 256 threads, 8x8 register tile per thread.
// Epilogues:
//   0 PLAIN : C[m*N+n] = acc
//   1 KV    : write [B,H,L,HD] transpose layout (for k/v outputs)
//   2 RESID : C = acc + R
//   3 RELU  : C = max(acc, 0)
#define BM 128
#define BN 128
#define BK 16
#define TM 8
#define TN 8

template<int EPI>
__global__ __launch_bounds__(256)
void sgemm_kernel(const float* __restrict__ A, const float* __restrict__ B,
                  float* __restrict__ C, const float* __restrict__ R,
                  int M, int N, int K)
{
    __shared__ __align__(16) float As[BK][BM + 4];
    __shared__ __align__(16) float Bs[BK][BN];

    const int bx = blockIdx.x;   // N tiles
    const int by = blockIdx.y;   // M tiles
    const int tid = threadIdx.x;
    const int tx = tid & 15;
    const int ty = tid >> 4;

    const float* Ab = A + (size_t)by * BM * K;
    const float* Bb = B + (size_t)bx * BN;

    // A tile load mapping: 128 rows x 4 float4 per row = 512 f4, 2 per thread
    const int a_row  = tid >> 2;        // 0..63
    const int a_col4 = tid & 3;         // f4 idx in row
    // B tile load mapping: 16 rows x 32 f4 = 512 f4, 2 per thread
    const int b_row  = tid >> 5;        // 0..7
    const int b_col4 = tid & 31;

    float acc[TM][TN];
    #pragma unroll
    for (int i = 0; i < TM; i++)
        #pragma unroll
        for (int j = 0; j < TN; j++) acc[i][j] = 0.0f;

    for (int k0 = 0; k0 < K; k0 += BK) {
        #pragma unroll
        for (int i = 0; i < 2; i++) {
            int r = a_row + i * 64;
            float4 v = *(const float4*)(Ab + (size_t)r * K + k0 + a_col4 * 4);
            As[a_col4*4 + 0][r] = v.x;
            As[a_col4*4 + 1][r] = v.y;
            As[a_col4*4 + 2][r] = v.z;
            As[a_col4*4 + 3][r] = v.w;
        }
        #pragma unroll
        for (int i = 0; i < 2; i++) {
            int r = b_row + i * 8;
            *(float4*)&Bs[r][b_col4 * 4] =
                *(const float4*)(Bb + (size_t)(k0 + r) * N + b_col4 * 4);
        }
        __syncthreads();

        #pragma unroll
        for (int kk = 0; kk < BK; kk++) {
            float4 a0 = *(const float4*)&As[kk][ty * TM];
            float4 a1 = *(const float4*)&As[kk][ty * TM + 4];
            float4 b0 = *(const float4*)&Bs[kk][tx * TN];
            float4 b1 = *(const float4*)&Bs[kk][tx * TN + 4];
            float a[TM] = {a0.x, a0.y, a0.z, a0.w, a1.x, a1.y, a1.z, a1.w};
            float b[TN] = {b0.x, b0.y, b0.z, b0.w, b1.x, b1.y, b1.z, b1.w};
            #pragma unroll
            for (int i = 0; i < TM; i++)
                #pragma unroll
                for (int j = 0; j < TN; j++)
                    acc[i][j] = fmaf(a[i], b[j], acc[i][j]);
        }
        __syncthreads();
    }

    const int m0 = by * BM + ty * TM;
    const int n0 = bx * BN + tx * TN;

    if (EPI == 1) {
        // KV transpose write: out[((b*H + h)*L + l)*HD + d]
        #pragma unroll
        for (int i = 0; i < TM; i++) {
            int mm = m0 + i;
            int b  = mm >> 10;          // / LT
            int l  = mm & 1023;
            #pragma unroll
            for (int j = 0; j < TN; j++) {
                int nn = n0 + j;
                int h = nn >> 6;
                int d = nn & 63;
                C[(((size_t)(b * HH + h) * LT + l) << 6) + d] = acc[i][j];
            }
        }
    } else {
        #pragma unroll
        for (int i = 0; i < TM; i++) {
            size_t off = (size_t)(m0 + i) * N + n0;
            #pragma unroll
            for (int j = 0; j < TN; j += 4) {
                float4 v = make_float4(acc[i][j], acc[i][j+1], acc[i][j+2], acc[i][j+3]);
                if (EPI == 2) {
                    float4 r = *(const float4*)(R + off + j);
                    v.x += r.x; v.y += r.y; v.z += r.z; v.w += r.w;
                }
                if (EPI == 3) {
                    v.x = fmaxf(v.x, 0.f); v.y = fmaxf(v.y, 0.f);
                    v.z = fmaxf(v.z, 0.f); v.w = fmaxf(v.w, 0.f);
                }
                *(float4*)(C + off + j) = v;
            }
        }
    }
}

// ---------------------------------------------------------------------------
// Fused flash attention (fp32, online softmax).
// Grid: (LT/64, H, B). 64 threads; thread t owns query row qt*64+t.
// Q layout: [B, L, H*HD] (row stride D). K/V layout: [B,H,L,HD].
// MODE 0: causal mask (tile skipping + diagonal mask)
// MODE 1: additive bias [H, LT, LS]
#define QT 64
#define CH 16   // softmax chunk (register pressure control)

template<int MODE>
__global__ __launch_bounds__(64)
void attn_kernel(const float* __restrict__ Q,
                 const float* __restrict__ Kt,
                 const float* __restrict__ Vt,
                 const float* __restrict__ bias,
                 float* __restrict__ O)
{
    const int qt  = blockIdx.x;
    const int h   = blockIdx.y;
    const int b   = blockIdx.z;
    const int tid = threadIdx.x;
    const int gq  = qt * QT + tid;

    __shared__ __align__(16) float Ks[QT][HD];
    __shared__ __align__(16) float Vs[QT][HD];
    __shared__ __align__(16) float Bi[(MODE == 1) ? QT * QT : 4];

    float q[HD], o[HD];
    #pragma unroll
    for (int d = 0; d < HD; d++) o[d] = 0.0f;

    const float* qptr = Q + ((size_t)(b * LT + gq)) * DD + h * HD;
    #pragma unroll
    for (int d = 0; d < HD; d += 4) {
        float4 v = *(const float4*)(qptr + d);
        q[d] = v.x; q[d+1] = v.y; q[d+2] = v.z; q[d+3] = v.w;
    }

    float m = -1e30f, l = 0.0f;
    const float scale = 0.125f;   // 1/sqrt(64)

    const float* Kb = Kt + ((size_t)(b * HH + h)) * LS * HD;
    const float* Vb = Vt + ((size_t)(b * HH + h)) * LS * HD;

    const int ktmax = (MODE == 0) ? qt : (LS / QT - 1);

    for (int kt = 0; kt <= ktmax; kt++) {
        // cooperative coalesced tile loads (64 threads, 1024 f4 each tile)
        {
            const float4* ksrc = (const float4*)(Kb + (size_t)kt * QT * HD);
            const float4* vsrc = (const float4*)(Vb + (size_t)kt * QT * HD);
            float4* kdst = (float4*)&Ks[0][0];
            float4* vdst = (float4*)&Vs[0][0];
            #pragma unroll
            for (int f = 0; f < QT * HD / 4; f += 64) {
                kdst[f + tid] = ksrc[f + tid];
                vdst[f + tid] = vsrc[f + tid];
            }
            if (MODE == 1) {
                // each thread stages its own bias row slice
                const float* brow = bias + ((size_t)h * LT + gq) * LS + kt * QT;
                float* bdst = &Bi[tid * QT];
                #pragma unroll
                for (int i = 0; i < QT; i += 4)
                    *(float4*)(bdst + i) = *(const float4*)(brow + i);
            }
        }
        __syncthreads();

        #pragma unroll
        for (int c = 0; c < QT / CH; c++) {
            float p[CH];
            float mc = -1e30f;
            #pragma unroll
            for (int kk = 0; kk < CH; kk++) {
                int k = c * CH + kk;
                float s = 0.0f;
                #pragma unroll
                for (int d = 0; d < HD; d += 4) {
                    float4 kv = *(const float4*)&Ks[k][d];
                    s = fmaf(q[d],   kv.x, s);
                    s = fmaf(q[d+1], kv.y, s);
                    s = fmaf(q[d+2], kv.z, s);
                    s = fmaf(q[d+3], kv.w, s);
                }
                s *= scale;
                if (MODE == 0) {
                    if (kt * QT + k > gq) s = -1e30f;
                } else {
                    s += Bi[tid * QT + k];
                }
                p[kk] = s;
                mc = fmaxf(mc, s);
            }
            float mnew = fmaxf(m, mc);
            float corr = __expf(m - mnew);
            l *= corr;
            #pragma unroll
            for (int d = 0; d < HD; d++) o[d] *= corr;
            m = mnew;
            #pragma unroll
            for (int kk = 0; kk < CH; kk++) {
                float pe = __expf(p[kk] - mnew);
                l += pe;
                int k = c * CH + kk;
                #pragma unroll
                for (int d = 0; d < HD; d += 4) {
                    float4 vv = *(const float4*)&Vs[k][d];
                    o[d]   = fmaf(pe, vv.x, o[d]);
                    o[d+1] = fmaf(pe, vv.y, o[d+1]);
                    o[d+2] = fmaf(pe, vv.z, o[d+2]);
                    o[d+3] = fmaf(pe, vv.w, o[d+3]);
                }
            }
        }
        __syncthreads();
    }

    float inv = 1.0f / l;
    float* optr = O + ((size_t)(b * LT + gq)) * DD + h * HD;
    #pragma unroll
    for (int d = 0; d < HD; d += 4) {
        float4 v = make_float4(o[d]*inv, o[d+1]*inv, o[d+2]*inv, o[d+3]*inv);
        *(float4*)(optr + d) = v;
    }
}

// ---------------------------------------------------------------------------
extern "C" void kernel_launch(void* const* d_in, const int* in_sizes, int n_in,
                              void* d_out, int out_size)
{
    const float* x        = (const float*)d_in[0];
    const float* memory   = (const float*)d_in[1];
    const float* pos_emb  = (const float*)d_in[2];
    // d_in[3] = causal_mask (implemented analytically)
    const float* gamma_sa = (const float*)d_in[4];
    const float* wq_s     = (const float*)d_in[5];
    const float* wk_s     = (const float*)d_in[6];
    const float* wv_s     = (const float*)d_in[7];
    const float* wo_s     = (const float*)d_in[8];
    const float* gamma_ca = (const float*)d_in[9];
    const float* wq_c     = (const float*)d_in[10];
    const float* wk_c     = (const float*)d_in[11];
    const float* wv_c     = (const float*)d_in[12];
    const float* wo_c     = (const float*)d_in[13];
    const float* gamma_m  = (const float*)d_in[14];
    const float* w1       = (const float*)d_in[15];
    const float* w2       = (const float*)d_in[16];

    float* scratch = nullptr;
    cudaGetSymbolAddress((void**)&scratch, g_scratch);
    float* bh    = scratch;
    float* bq    = scratch + (size_t)1 * SLOT;
    float* battn = scratch + (size_t)2 * SLOT;
    float* bx1   = scratch + (size_t)3 * SLOT;
    float* bx2   = scratch + (size_t)4 * SLOT;
    float* bffn  = scratch + (size_t)5 * SLOT;

    float* out   = (float*)d_out;
    float* o_mlp = out;
    float* o_ks  = out + (size_t)1 * SLOT;
    float* o_vs  = out + (size_t)2 * SLOT;
    float* o_kc  = out + (size_t)3 * SLOT;
    float* o_vc  = out + (size_t)4 * SLOT;

    const dim3 gD(DD / BN, MTOT / BM);    // N=1024 output GEMMs
    const dim3 gF(FF / BN, MTOT / BM);    // N=4096 (FFN up)
    const dim3 gA(LT / QT, HH, BB);       // attention

    // ---- self-attention block ----
    rmsnorm_kernel<<<MTOT, 256>>>(x, gamma_sa, bh);
    sgemm_kernel<0><<<gD, 256>>>(bh, wq_s, bq,   nullptr, MTOT, DD, DD);
    sgemm_kernel<1><<<gD, 256>>>(bh, wk_s, o_ks, nullptr, MTOT, DD, DD);
    sgemm_kernel<1><<<gD, 256>>>(bh, wv_s, o_vs, nullptr, MTOT, DD, DD);
    attn_kernel<0><<<gA, 64>>>(bq, o_ks, o_vs, nullptr, battn);
    sgemm_kernel<2><<<gD, 256>>>(battn, wo_s, bx1, x, MTOT, DD, DD);

    // ---- cross-attention block ----
    rmsnorm_kernel<<<MTOT, 256>>>(bx1, gamma_ca, bh);
    sgemm_kernel<0><<<gD, 256>>>(bh,     wq_c, bq,   nullptr, MTOT, DD, DD);
    sgemm_kernel<1><<<gD, 256>>>(memory, wk_c, o_kc, nullptr, MTOT, DD, DD);
    sgemm_kernel<1><<<gD, 256>>>(memory, wv_c, o_vc, nullptr, MTOT, DD, DD);
    attn_kernel<1><<<gA, 64>>>(bq, o_kc, o_vc, pos_emb, battn);
    sgemm_kernel<2><<<gD, 256>>>(battn, wo_c, bx2, bx1, MTOT, DD, DD);

    // ---- FFN block ----
    rmsnorm_kernel<<<MTOT, 256>>>(bx2, gamma_m, bh);
    sgemm_kernel<3><<<gF, 256>>>(bh,   w1, bffn,  nullptr, MTOT, FF, DD);
    sgemm_kernel<2><<<gD, 256>>>(bffn, w2, o_mlp, bx2,     MTOT, DD, FF);
}

// round 2
// speedup vs baseline: 1.7536x; 1.7536x over previous
#include <cuda_runtime.h>
#include <cuda_bf16.h>
#include <cstdint>

// Problem constants
#define BB 4
#define LT 1024
#define LS 1024
#define DD 1024
#define HH 16
#define HD 64
#define FF 4096
#define MTOT (BB*LT)   // 4096 rows

#define SLOT (MTOT*DD)                     // 4M floats
__device__ float g_scratch[5*SLOT + MTOT*FF];

// ---------------------------------------------------------------------------
// RMSNorm
__global__ void rmsnorm_kernel(const float* __restrict__ x,
                               const float* __restrict__ g,
                               float* __restrict__ out)
{
    __shared__ float red[256];
    int row = blockIdx.x;
    int tid = threadIdx.x;
    const float4* xr = (const float4*)(x + (size_t)row * DD);
    float4 v = xr[tid];
    float ss = v.x*v.x + v.y*v.y + v.z*v.z + v.w*v.w;
    red[tid] = ss;
    __syncthreads();
    #pragma unroll
    for (int s = 128; s > 0; s >>= 1) {
        if (tid < s) red[tid] += red[tid + s];
        __syncthreads();
    }
    float inv = rsqrtf(red[0] * (1.0f/(float)DD) + 1e-6f);
    const float4 gg = ((const float4*)g)[tid];
    float4 o;
    o.x = v.x * inv * gg.x;
    o.y = v.y * inv * gg.y;
    o.z = v.z * inv * gg.z;
    o.w = v.w * inv * gg.w;
    ((float4*)(out + (size_t)row * DD))[tid] = o;
}

// ---------------------------------------------------------------------------
// TF32 tensor-core GEMM: C[M,N] = A[M,K] @ B[K,N], fp32 in/out, tf32 mma.
// 128x128x32 tiles, 256 threads (8 warps, 2x4), warp tile 64x32 (4x4 m16n8k8).
// cp.async double-buffered. Epilogues: 0 plain, 1 KV-transpose, 2 resid, 3 relu.
#define TC_BM 128
#define TC_BN 128
#define TC_BK 32
#define AS_STRIDE (TC_BK + 8)          // 40  -> frag bank = (8g+t), conflict-free
#define BS_STRIDE (TC_BN + 8)          // 136 -> frag bank = (8t+g), conflict-free
#define AS_ELEMS (TC_BM * AS_STRIDE)   // 5120
#define BS_ELEMS (TC_BK * BS_STRIDE)   // 4352
#define TC_SMEM_BYTES (2 * (AS_ELEMS + BS_ELEMS) * 4)  // 75776

__device__ __forceinline__ uint32_t f2tf32(float f) {
    uint32_t u;
    asm("cvt.rna.tf32.f32 %0, %1;" : "=r"(u) : "f"(f));
    return u;
}

__device__ __forceinline__ void mma_tf32(float* d, const uint32_t* a, const uint32_t* b) {
    asm volatile(
        "mma.sync.aligned.m16n8k8.row.col.f32.tf32.tf32.f32 "
        "{%0,%1,%2,%3}, {%4,%5,%6,%7}, {%8,%9}, {%0,%1,%2,%3};"
        : "+f"(d[0]), "+f"(d[1]), "+f"(d[2]), "+f"(d[3])
        : "r"(a[0]), "r"(a[1]), "r"(a[2]), "r"(a[3]), "r"(b[0]), "r"(b[1]));
}

__device__ __forceinline__ void cp16(uint32_t dst, const float* src) {
    asm volatile("cp.async.cg.shared.global [%0], [%1], 16;" :: "r"(dst), "l"(src));
}

template<int EPI>
__global__ __launch_bounds__(256)
void tc_gemm(const float* __restrict__ A, const float* __restrict__ B,
             float* __restrict__ C, const float* __restrict__ R,
             int M, int N, int K)
{
    extern __shared__ float sm[];
    float* As0 = sm;
    float* As1 = sm + AS_ELEMS;
    float* Bs0 = sm + 2 * AS_ELEMS;
    float* Bs1 = sm + 2 * AS_ELEMS + BS_ELEMS;

    const int tid  = threadIdx.x;
    const int wid  = tid >> 5;
    const int lane = tid & 31;
    const int g    = lane >> 2;
    const int t    = lane & 3;
    const int wm   = wid & 1;       // 0..1
    const int wn   = wid >> 1;      // 0..3
    const int m0   = blockIdx.y * TC_BM;
    const int n0   = blockIdx.x * TC_BN;

    // loader mapping
    const int a_m = tid >> 3;            // 0..31 (+p*32)
    const int a_c = (tid & 7) * 4;       // float col within BK
    const int b_k = tid >> 5;            // 0..7  (+p*8)
    const int b_c = (tid & 31) * 4;      // float col within BN

    const uint32_t asm0 = (uint32_t)__cvta_generic_to_shared(As0);
    const uint32_t asm1 = (uint32_t)__cvta_generic_to_shared(As1);
    const uint32_t bsm0 = (uint32_t)__cvta_generic_to_shared(Bs0);
    const uint32_t bsm1 = (uint32_t)__cvta_generic_to_shared(Bs1);

    float acc[4][4][4];
    #pragma unroll
    for (int mi = 0; mi < 4; mi++)
        #pragma unroll
        for (int ni = 0; ni < 4; ni++)
            #pragma unroll
            for (int r = 0; r < 4; r++) acc[mi][ni][r] = 0.0f;

    const int NT = K / TC_BK;

    // issue tile 0
    {
        #pragma unroll
        for (int p = 0; p < 4; p++) {
            int r = a_m + p * 32;
            cp16(asm0 + (uint32_t)((r * AS_STRIDE + a_c) << 2),
                 A + (size_t)(m0 + r) * K + a_c);
        }
        #pragma unroll
        for (int p = 0; p < 4; p++) {
            int r = b_k + p * 8;
            cp16(bsm0 + (uint32_t)((r * BS_STRIDE + b_c) << 2),
                 B + (size_t)r * N + n0 + b_c);
        }
        asm volatile("cp.async.commit_group;");
    }

    for (int kt = 0; kt < NT; kt++) {
        const int cur = kt & 1;
        if (kt + 1 < NT) {
            const int k0 = (kt + 1) * TC_BK;
            uint32_t ad = cur ? asm0 : asm1;
            uint32_t bd = cur ? bsm0 : bsm1;
            #pragma unroll
            for (int p = 0; p < 4; p++) {
                int r = a_m + p * 32;
                cp16(ad + (uint32_t)((r * AS_STRIDE + a_c) << 2),
                     A + (size_t)(m0 + r) * K + k0 + a_c);
            }
            #pragma unroll
            for (int p = 0; p < 4; p++) {
                int r = b_k + p * 8;
                cp16(bd + (uint32_t)((r * BS_STRIDE + b_c) << 2),
                     B + (size_t)(k0 + r) * N + n0 + b_c);
            }
            asm volatile("cp.async.commit_group;");
            asm volatile("cp.async.wait_group 1;");
        } else {
            asm volatile("cp.async.wait_group 0;");
        }
        __syncthreads();

        const float* Ab = (cur ? As1 : As0) + (wm * 64 + g) * AS_STRIDE + t;
        const float* Bb = (cur ? Bs1 : Bs0) + t * BS_STRIDE + wn * 32 + g;

        #pragma unroll
        for (int kk = 0; kk < 4; kk++) {
            uint32_t af[4][4];
            uint32_t bf[4][2];
            #pragma unroll
            for (int mi = 0; mi < 4; mi++) {
                const float* p = Ab + mi * 16 * AS_STRIDE + kk * 8;
                af[mi][0] = f2tf32(p[0]);
                af[mi][1] = f2tf32(p[8 * AS_STRIDE]);
                af[mi][2] = f2tf32(p[4]);
                af[mi][3] = f2tf32(p[8 * AS_STRIDE + 4]);
            }
            #pragma unroll
            for (int ni = 0; ni < 4; ni++) {
                const float* p = Bb + kk * 8 * BS_STRIDE + ni * 8;
                bf[ni][0] = f2tf32(p[0]);
                bf[ni][1] = f2tf32(p[4 * BS_STRIDE]);
            }
            #pragma unroll
            for (int mi = 0; mi < 4; mi++)
                #pragma unroll
                for (int ni = 0; ni < 4; ni++)
                    mma_tf32(acc[mi][ni], af[mi], bf[ni]);
        }
        __syncthreads();
    }

    // epilogue
    const int mbase = m0 + wm * 64 + g;
    const int nbase = n0 + wn * 32 + 2 * t;

    if (EPI == 1) {
        // KV transpose write: out[((b*H + h)*L + l)*HD + d]
        #pragma unroll
        for (int mi = 0; mi < 4; mi++) {
            #pragma unroll
            for (int ni = 0; ni < 4; ni++) {
                #pragma unroll
                for (int half = 0; half < 2; half++) {
                    int m = mbase + mi * 16 + half * 8;
                    int b = m >> 10, l = m & 1023;
                    #pragma unroll
                    for (int c = 0; c < 2; c++) {
                        int n = nbase + ni * 8 + c;
                        int h = n >> 6, d = n & 63;
                        C[(((size_t)(b * HH + h) * LT + l) << 6) + d] =
                            acc[mi][ni][half * 2 + c];
                    }
                }
            }
        }
    } else {
        #pragma unroll
        for (int mi = 0; mi < 4; mi++) {
            #pragma unroll
            for (int ni = 0; ni < 4; ni++) {
                int n = nbase + ni * 8;
                #pragma unroll
                for (int half = 0; half < 2; half++) {
                    int m = mbase + mi * 16 + half * 8;
                    size_t off = (size_t)m * N + n;
                    float2 v = make_float2(acc[mi][ni][half * 2], acc[mi][ni][half * 2 + 1]);
                    if (EPI == 2) {
                        float2 r = *(const float2*)(R + off);
                        v.x += r.x; v.y += r.y;
                    }
                    if (EPI == 3) {
                        v.x = fmaxf(v.x, 0.f); v.y = fmaxf(v.y, 0.f);
                    }
                    *(float2*)(C + off) = v;
                }
            }
        }
    }
}

// ---------------------------------------------------------------------------
// Fused flash attention (fp32, online softmax) — unchanged from R1.
#define QT 64
#define CH 16

template<int MODE>
__global__ __launch_bounds__(64)
void attn_kernel(const float* __restrict__ Q,
                 const float* __restrict__ Kt,
                 const float* __restrict__ Vt,
                 const float* __restrict__ bias,
                 float* __restrict__ O)
{
    const int qt  = blockIdx.x;
    const int h   = blockIdx.y;
    const int b   = blockIdx.z;
    const int tid = threadIdx.x;
    const int gq  = qt * QT + tid;

    __shared__ __align__(16) float Ks[QT][HD];
    __shared__ __align__(16) float Vs[QT][HD];
    __shared__ __align__(16) float Bi[(MODE == 1) ? QT * QT : 4];

    float q[HD], o[HD];
    #pragma unroll
    for (int d = 0; d < HD; d++) o[d] = 0.0f;

    const float* qptr = Q + ((size_t)(b * LT + gq)) * DD + h * HD;
    #pragma unroll
    for (int d = 0; d < HD; d += 4) {
        float4 v = *(const float4*)(qptr + d);
        q[d] = v.x; q[d+1] = v.y; q[d+2] = v.z; q[d+3] = v.w;
    }

    float m = -1e30f, l = 0.0f;
    const float scale = 0.125f;

    const float* Kb = Kt + ((size_t)(b * HH + h)) * LS * HD;
    const float* Vb = Vt + ((size_t)(b * HH + h)) * LS * HD;

    const int ktmax = (MODE == 0) ? qt : (LS / QT - 1);

    for (int kt = 0; kt <= ktmax; kt++) {
        {
            const float4* ksrc = (const float4*)(Kb + (size_t)kt * QT * HD);
            const float4* vsrc = (const float4*)(Vb + (size_t)kt * QT * HD);
            float4* kdst = (float4*)&Ks[0][0];
            float4* vdst = (float4*)&Vs[0][0];
            #pragma unroll
            for (int f = 0; f < QT * HD / 4; f += 64) {
                kdst[f + tid] = ksrc[f + tid];
                vdst[f + tid] = vsrc[f + tid];
            }
            if (MODE == 1) {
                const float* brow = bias + ((size_t)h * LT + gq) * LS + kt * QT;
                float* bdst = &Bi[tid * QT];
                #pragma unroll
                for (int i = 0; i < QT; i += 4)
                    *(float4*)(bdst + i) = *(const float4*)(brow + i);
            }
        }
        __syncthreads();

        #pragma unroll
        for (int c = 0; c < QT / CH; c++) {
            float p[CH];
            float mc = -1e30f;
            #pragma unroll
            for (int kk = 0; kk < CH; kk++) {
                int k = c * CH + kk;
                float s = 0.0f;
                #pragma unroll
                for (int d = 0; d < HD; d += 4) {
                    float4 kv = *(const float4*)&Ks[k][d];
                    s = fmaf(q[d],   kv.x, s);
                    s = fmaf(q[d+1], kv.y, s);
                    s = fmaf(q[d+2], kv.z, s);
                    s = fmaf(q[d+3], kv.w, s);
                }
                s *= scale;
                if (MODE == 0) {
                    if (kt * QT + k > gq) s = -1e30f;
                } else {
                    s += Bi[tid * QT + k];
                }
                p[kk] = s;
                mc = fmaxf(mc, s);
            }
            float mnew = fmaxf(m, mc);
            float corr = __expf(m - mnew);
            l *= corr;
            #pragma unroll
            for (int d = 0; d < HD; d++) o[d] *= corr;
            m = mnew;
            #pragma unroll
            for (int kk = 0; kk < CH; kk++) {
                float pe = __expf(p[kk] - mnew);
                l += pe;
                int k = c * CH + kk;
                #pragma unroll
                for (int d = 0; d < HD; d += 4) {
                    float4 vv = *(const float4*)&Vs[k][d];
                    o[d]   = fmaf(pe, vv.x, o[d]);
                    o[d+1] = fmaf(pe, vv.y, o[d+1]);
                    o[d+2] = fmaf(pe, vv.z, o[d+2]);
                    o[d+3] = fmaf(pe, vv.w, o[d+3]);
                }
            }
        }
        __syncthreads();
    }

    float inv = 1.0f / l;
    float* optr = O + ((size_t)(b * LT + gq)) * DD + h * HD;
    #pragma unroll
    for (int d = 0; d < HD; d += 4) {
        float4 v = make_float4(o[d]*inv, o[d+1]*inv, o[d+2]*inv, o[d+3]*inv);
        *(float4*)(optr + d) = v;
    }
}

// ---------------------------------------------------------------------------
extern "C" void kernel_launch(void* const* d_in, const int* in_sizes, int n_in,
                              void* d_out, int out_size)
{
    const float* x        = (const float*)d_in[0];
    const float* memory   = (const float*)d_in[1];
    const float* pos_emb  = (const float*)d_in[2];
    const float* gamma_sa = (const float*)d_in[4];
    const float* wq_s     = (const float*)d_in[5];
    const float* wk_s     = (const float*)d_in[6];
    const float* wv_s     = (const float*)d_in[7];
    const float* wo_s     = (const float*)d_in[8];
    const float* gamma_ca = (const float*)d_in[9];
    const float* wq_c     = (const float*)d_in[10];
    const float* wk_c     = (const float*)d_in[11];
    const float* wv_c     = (const float*)d_in[12];
    const float* wo_c     = (const float*)d_in[13];
    const float* gamma_m  = (const float*)d_in[14];
    const float* w1       = (const float*)d_in[15];
    const float* w2       = (const float*)d_in[16];

    float* scratch = nullptr;
    cudaGetSymbolAddress((void**)&scratch, g_scratch);
    float* bh    = scratch;
    float* bq    = scratch + (size_t)1 * SLOT;
    float* battn = scratch + (size_t)2 * SLOT;
    float* bx1   = scratch + (size_t)3 * SLOT;
    float* bx2   = scratch + (size_t)4 * SLOT;
    float* bffn  = scratch + (size_t)5 * SLOT;

    float* out   = (float*)d_out;
    float* o_mlp = out;
    float* o_ks  = out + (size_t)1 * SLOT;
    float* o_vs  = out + (size_t)2 * SLOT;
    float* o_kc  = out + (size_t)3 * SLOT;
    float* o_vc  = out + (size_t)4 * SLOT;

    static bool attr_set = false;
    if (!attr_set) {
        cudaFuncSetAttribute(tc_gemm<0>, cudaFuncAttributeMaxDynamicSharedMemorySize, TC_SMEM_BYTES);
        cudaFuncSetAttribute(tc_gemm<1>, cudaFuncAttributeMaxDynamicSharedMemorySize, TC_SMEM_BYTES);
        cudaFuncSetAttribute(tc_gemm<2>, cudaFuncAttributeMaxDynamicSharedMemorySize, TC_SMEM_BYTES);
        cudaFuncSetAttribute(tc_gemm<3>, cudaFuncAttributeMaxDynamicSharedMemorySize, TC_SMEM_BYTES);
        attr_set = true;
    }

    const dim3 gD(DD / TC_BN, MTOT / TC_BM);   // (8, 32)
    const dim3 gF(FF / TC_BN, MTOT / TC_BM);   // (32, 32)
    const dim3 gA(LT / QT, HH, BB);

    // ---- self-attention block ----
    rmsnorm_kernel<<<MTOT, 256>>>(x, gamma_sa, bh);
    tc_gemm<0><<<gD, 256, TC_SMEM_BYTES>>>(bh, wq_s, bq,   nullptr, MTOT, DD, DD);
    tc_gemm<1><<<gD, 256, TC_SMEM_BYTES>>>(bh, wk_s, o_ks, nullptr, MTOT, DD, DD);
    tc_gemm<1><<<gD, 256, TC_SMEM_BYTES>>>(bh, wv_s, o_vs, nullptr, MTOT, DD, DD);
    attn_kernel<0><<<gA, 64>>>(bq, o_ks, o_vs, nullptr, battn);
    tc_gemm<2><<<gD, 256, TC_SMEM_BYTES>>>(battn, wo_s, bx1, x, MTOT, DD, DD);

    // ---- cross-attention block ----
    rmsnorm_kernel<<<MTOT, 256>>>(bx1, gamma_ca, bh);
    tc_gemm<0><<<gD, 256, TC_SMEM_BYTES>>>(bh,     wq_c, bq,   nullptr, MTOT, DD, DD);
    tc_gemm<1><<<gD, 256, TC_SMEM_BYTES>>>(memory, wk_c, o_kc, nullptr, MTOT, DD, DD);
    tc_gemm<1><<<gD, 256, TC_SMEM_BYTES>>>(memory, wv_c, o_vc, nullptr, MTOT, DD, DD);
    attn_kernel<1><<<gA, 64>>>(bq, o_kc, o_vc, pos_emb, battn);
    tc_gemm<2><<<gD, 256, TC_SMEM_BYTES>>>(battn, wo_c, bx2, bx1, MTOT, DD, DD);

    // ---- FFN block ----
    rmsnorm_kernel<<<MTOT, 256>>>(bx2, gamma_m, bh);
    tc_gemm<3><<<gF, 256, TC_SMEM_BYTES>>>(bh,   w1, bffn,  nullptr, MTOT, FF, DD);
    tc_gemm<2><<<gD, 256, TC_SMEM_BYTES>>>(bffn, w2, o_mlp, bx2,     MTOT, DD, FF);
}

// round 5
// speedup vs baseline: 3.9361x; 2.2446x over previous
#include <cuda_runtime.h>
#include <cuda_bf16.h>
#include <cstdint>

// Problem constants
#define BB 4
#define LT 1024
#define LS 1024
#define DD 1024
#define HH 16
#define HD 64
#define FF 4096
#define MTOT (BB*LT)   // 4096 rows

#define SLOT (MTOT*DD)                     // 4M floats
__device__ float g_scratch[5*SLOT + MTOT*FF];

// ---------------------------------------------------------------------------
// RMSNorm
__global__ void rmsnorm_kernel(const float* __restrict__ x,
                               const float* __restrict__ g,
                               float* __restrict__ out)
{
    __shared__ float red[256];
    int row = blockIdx.x;
    int tid = threadIdx.x;
    const float4* xr = (const float4*)(x + (size_t)row * DD);
    float4 v = xr[tid];
    float ss = v.x*v.x + v.y*v.y + v.z*v.z + v.w*v.w;
    red[tid] = ss;
    __syncthreads();
    #pragma unroll
    for (int s = 128; s > 0; s >>= 1) {
        if (tid < s) red[tid] += red[tid + s];
        __syncthreads();
    }
    float inv = rsqrtf(red[0] * (1.0f/(float)DD) + 1e-6f);
    const float4 gg = ((const float4*)g)[tid];
    float4 o;
    o.x = v.x * inv * gg.x;
    o.y = v.y * inv * gg.y;
    o.z = v.z * inv * gg.z;
    o.w = v.w * inv * gg.w;
    ((float4*)(out + (size_t)row * DD))[tid] = o;
}

// ---------------------------------------------------------------------------
// Common tensor-core helpers
__device__ __forceinline__ uint32_t f2tf32(float f) {
    uint32_t u;
    asm("cvt.rna.tf32.f32 %0, %1;" : "=r"(u) : "f"(f));
    return u;
}

__device__ __forceinline__ void mma_tf32(float* d, const uint32_t* a, const uint32_t* b) {
    asm volatile(
        "mma.sync.aligned.m16n8k8.row.col.f32.tf32.tf32.f32 "
        "{%0,%1,%2,%3}, {%4,%5,%6,%7}, {%8,%9}, {%0,%1,%2,%3};"
        : "+f"(d[0]), "+f"(d[1]), "+f"(d[2]), "+f"(d[3])
        : "r"(a[0]), "r"(a[1]), "r"(a[2]), "r"(a[3]), "r"(b[0]), "r"(b[1]));
}

__device__ __forceinline__ void cp16(uint32_t dst, const float* src) {
    asm volatile("cp.async.cg.shared.global [%0], [%1], 16;" :: "r"(dst), "l"(src));
}

// ---------------------------------------------------------------------------
// TF32 tensor-core GEMM (unchanged, proven at R2)
#define TC_BM 128
#define TC_BN 128
#define TC_BK 32
#define AS_STRIDE (TC_BK + 8)
#define BS_STRIDE (TC_BN + 8)
#define AS_ELEMS (TC_BM * AS_STRIDE)
#define BS_ELEMS (TC_BK * BS_STRIDE)
#define TC_SMEM_BYTES (2 * (AS_ELEMS + BS_ELEMS) * 4)

template<int EPI>
__global__ __launch_bounds__(256)
void tc_gemm(const float* __restrict__ A, const float* __restrict__ B,
             float* __restrict__ C, const float* __restrict__ R,
             int M, int N, int K)
{
    extern __shared__ float sm[];
    float* As0 = sm;
    float* As1 = sm + AS_ELEMS;
    float* Bs0 = sm + 2 * AS_ELEMS;
    float* Bs1 = sm + 2 * AS_ELEMS + BS_ELEMS;

    const int tid  = threadIdx.x;
    const int wid  = tid >> 5;
    const int lane = tid & 31;
    const int g    = lane >> 2;
    const int t    = lane & 3;
    const int wm   = wid & 1;
    const int wn   = wid >> 1;
    const int m0   = blockIdx.y * TC_BM;
    const int n0   = blockIdx.x * TC_BN;

    const int a_m = tid >> 3;
    const int a_c = (tid & 7) * 4;
    const int b_k = tid >> 5;
    const int b_c = (tid & 31) * 4;

    const uint32_t asm0 = (uint32_t)__cvta_generic_to_shared(As0);
    const uint32_t asm1 = (uint32_t)__cvta_generic_to_shared(As1);
    const uint32_t bsm0 = (uint32_t)__cvta_generic_to_shared(Bs0);
    const uint32_t bsm1 = (uint32_t)__cvta_generic_to_shared(Bs1);

    float acc[4][4][4];
    #pragma unroll
    for (int mi = 0; mi < 4; mi++)
        #pragma unroll
        for (int ni = 0; ni < 4; ni++)
            #pragma unroll
            for (int r = 0; r < 4; r++) acc[mi][ni][r] = 0.0f;

    const int NT = K / TC_BK;

    {
        #pragma unroll
        for (int p = 0; p < 4; p++) {
            int r = a_m + p * 32;
            cp16(asm0 + (uint32_t)((r * AS_STRIDE + a_c) << 2),
                 A + (size_t)(m0 + r) * K + a_c);
        }
        #pragma unroll
        for (int p = 0; p < 4; p++) {
            int r = b_k + p * 8;
            cp16(bsm0 + (uint32_t)((r * BS_STRIDE + b_c) << 2),
                 B + (size_t)r * N + n0 + b_c);
        }
        asm volatile("cp.async.commit_group;");
    }

    for (int kt = 0; kt < NT; kt++) {
        const int cur = kt & 1;
        if (kt + 1 < NT) {
            const int k0 = (kt + 1) * TC_BK;
            uint32_t ad = cur ? asm0 : asm1;
            uint32_t bd = cur ? bsm0 : bsm1;
            #pragma unroll
            for (int p = 0; p < 4; p++) {
                int r = a_m + p * 32;
                cp16(ad + (uint32_t)((r * AS_STRIDE + a_c) << 2),
                     A + (size_t)(m0 + r) * K + k0 + a_c);
            }
            #pragma unroll
            for (int p = 0; p < 4; p++) {
                int r = b_k + p * 8;
                cp16(bd + (uint32_t)((r * BS_STRIDE + b_c) << 2),
                     B + (size_t)(k0 + r) * N + n0 + b_c);
            }
            asm volatile("cp.async.commit_group;");
            asm volatile("cp.async.wait_group 1;");
        } else {
            asm volatile("cp.async.wait_group 0;");
        }
        __syncthreads();

        const float* Ab = (cur ? As1 : As0) + (wm * 64 + g) * AS_STRIDE + t;
        const float* Bb = (cur ? Bs1 : Bs0) + t * BS_STRIDE + wn * 32 + g;

        #pragma unroll
        for (int kk = 0; kk < 4; kk++) {
            uint32_t af[4][4];
            uint32_t bf[4][2];
            #pragma unroll
            for (int mi = 0; mi < 4; mi++) {
                const float* p = Ab + mi * 16 * AS_STRIDE + kk * 8;
                af[mi][0] = f2tf32(p[0]);
                af[mi][1] = f2tf32(p[8 * AS_STRIDE]);
                af[mi][2] = f2tf32(p[4]);
                af[mi][3] = f2tf32(p[8 * AS_STRIDE + 4]);
            }
            #pragma unroll
            for (int ni = 0; ni < 4; ni++) {
                const float* p = Bb + kk * 8 * BS_STRIDE + ni * 8;
                bf[ni][0] = f2tf32(p[0]);
                bf[ni][1] = f2tf32(p[4 * BS_STRIDE]);
            }
            #pragma unroll
            for (int mi = 0; mi < 4; mi++)
                #pragma unroll
                for (int ni = 0; ni < 4; ni++)
                    mma_tf32(acc[mi][ni], af[mi], bf[ni]);
        }
        __syncthreads();
    }

    const int mbase = m0 + wm * 64 + g;
    const int nbase = n0 + wn * 32 + 2 * t;

    if (EPI == 1) {
        #pragma unroll
        for (int mi = 0; mi < 4; mi++) {
            #pragma unroll
            for (int ni = 0; ni < 4; ni++) {
                #pragma unroll
                for (int half = 0; half < 2; half++) {
                    int m = mbase + mi * 16 + half * 8;
                    int b = m >> 10, l = m & 1023;
                    #pragma unroll
                    for (int c = 0; c < 2; c++) {
                        int n = nbase + ni * 8 + c;
                        int h = n >> 6, d = n & 63;
                        C[(((size_t)(b * HH + h) * LT + l) << 6) + d] =
                            acc[mi][ni][half * 2 + c];
                    }
                }
            }
        }
    } else {
        #pragma unroll
        for (int mi = 0; mi < 4; mi++) {
            #pragma unroll
            for (int ni = 0; ni < 4; ni++) {
                int n = nbase + ni * 8;
                #pragma unroll
                for (int half = 0; half < 2; half++) {
                    int m = mbase + mi * 16 + half * 8;
                    size_t off = (size_t)m * N + n;
                    float2 v = make_float2(acc[mi][ni][half * 2], acc[mi][ni][half * 2 + 1]);
                    if (EPI == 2) {
                        float2 r = *(const float2*)(R + off);
                        v.x += r.x; v.y += r.y;
                    }
                    if (EPI == 3) {
                        v.x = fmaxf(v.x, 0.f); v.y = fmaxf(v.y, 0.f);
                    }
                    *(float2*)(C + off) = v;
                }
            }
        }
    }
}

// ---------------------------------------------------------------------------
// Tensor-core flash attention (tf32 mma, online softmax).
// Block: 128 threads (4 warps) handles 64 query rows of one (b,h).
// Warp w owns rows 16w..16w+15.
// Smem float offsets:
//   Qs   @ 0      : 64 x 68
//   Ks0  @ 4352   : 64 x 68   (key-major [key][d])
//   Ks1  @ 8704
//   Vs0  @ 13056  : 64 x 72
//   Vs1  @ 17664
//   Ps   @ 22272  : 64 x 68   (P as tf32 bits)
//   Bi0  @ 26624  : 64 x 68   (MODE 1 only)
//   Bi1  @ 30976
#define ATT_SMEM0 (26624 * 4)
#define ATT_SMEM1 (35328 * 4)

// Tile loader: 64 rows x 64 floats = 1024 16B chunks, 8 per thread (128 thr)
#define LOAD_TILE(dstoff, srcptr, srcstride, STRIDE)                          \
    _Pragma("unroll")                                                         \
    for (int i_ = 0; i_ < 8; i_++) {                                          \
        int idx_ = tid + i_ * 128;                                            \
        int r_ = idx_ >> 4, c_ = (idx_ & 15) * 4;                             \
        cp16(sbase + (uint32_t)(((dstoff) + r_ * (STRIDE) + c_) << 2),        \
             (srcptr) + (size_t)r_ * (srcstride) + c_);                       \
    }

template<int MODE>
__global__ __launch_bounds__(128)
void attn_tc(const float* __restrict__ Q, const float* __restrict__ K,
             const float* __restrict__ V, const float* __restrict__ bias,
             float* __restrict__ O)
{
    extern __shared__ float smf[];
    const int tid  = threadIdx.x;
    const int wid  = tid >> 5;
    const int lane = tid & 31;
    const int g    = lane >> 2;
    const int t    = lane & 3;
    const int qt   = blockIdx.x;
    const int h    = blockIdx.y;
    const int b    = blockIdx.z;

    const uint32_t sbase = (uint32_t)__cvta_generic_to_shared(smf);

    const float* Qg = Q + ((size_t)(b * LT) + qt * 64) * DD + h * HD;
    const float* Kg = K + ((size_t)(b * HH + h)) * LS * HD;
    const float* Vg = V + ((size_t)(b * HH + h)) * LS * HD;
    const float* Bg = (MODE == 1) ? bias + ((size_t)h * LT + qt * 64) * LS : nullptr;

    // ---- load Q tile + prefetch K/V (bias) tile 0 ----
    {
        LOAD_TILE(0,     Qg, DD, 68);
        LOAD_TILE(4352,  Kg, HD, 68);
        LOAD_TILE(13056, Vg, HD, 72);
        if (MODE == 1) {
            LOAD_TILE(26624, Bg, LS, 68);
        }
        asm volatile("cp.async.commit_group;");
    }

    float oacc[8][4];
    #pragma unroll
    for (int ni = 0; ni < 8; ni++)
        #pragma unroll
        for (int r = 0; r < 4; r++) oacc[ni][r] = 0.0f;

    float mrow[2] = { -1e30f, -1e30f };
    float lrow[2] = { 0.0f, 0.0f };

    const int ktmax = (MODE == 0) ? qt : (LS / 64 - 1);

    for (int kt = 0; kt <= ktmax; kt++) {
        const int cur = kt & 1;
        __syncthreads();   // all warps done with buffer cur^1 (retired tile)
        if (kt + 1 <= ktmax) {
            const int nk = kt + 1;
            const uint32_t koff = (cur == 0) ? 8704u  : 4352u;
            const uint32_t voff = (cur == 0) ? 17664u : 13056u;
            const float* kp = Kg + (size_t)nk * 64 * HD;
            const float* vp = Vg + (size_t)nk * 64 * HD;
            LOAD_TILE(koff, kp, HD, 68);
            LOAD_TILE(voff, vp, HD, 72);
            if (MODE == 1) {
                const uint32_t boff = (cur == 0) ? 30976u : 26624u;
                const float* bp = Bg + (size_t)nk * 64;
                LOAD_TILE(boff, bp, LS, 68);
            }
            asm volatile("cp.async.commit_group;");
            asm volatile("cp.async.wait_group 1;");
        } else {
            asm volatile("cp.async.wait_group 0;");
        }
        __syncthreads();

        const float* Ksc = smf + (cur ? 8704 : 4352);
        const float* Vsc = smf + (cur ? 17664 : 13056);
        const float* Bic = smf + (cur ? 30976 : 26624);

        // ---- S = Q K^T ----
        float sacc[8][4];
        #pragma unroll
        for (int ni = 0; ni < 8; ni++)
            #pragma unroll
            for (int r = 0; r < 4; r++) sacc[ni][r] = 0.0f;

        {
            const float* qb = smf + (wid * 16 + g) * 68 + t;
            const float* kb = Ksc + g * 68 + t;
            #pragma unroll
            for (int kk = 0; kk < 8; kk++) {
                uint32_t a[4];
                a[0] = f2tf32(qb[kk * 8]);
                a[1] = f2tf32(qb[8 * 68 + kk * 8]);
                a[2] = f2tf32(qb[kk * 8 + 4]);
                a[3] = f2tf32(qb[8 * 68 + kk * 8 + 4]);
                #pragma unroll
                for (int ni = 0; ni < 8; ni++) {
                    uint32_t bf[2];
                    bf[0] = f2tf32(kb[ni * 8 * 68 + kk * 8]);
                    bf[1] = f2tf32(kb[ni * 8 * 68 + kk * 8 + 4]);
                    mma_tf32(sacc[ni], a, bf);
                }
            }
        }

        // ---- softmax (per half-row), write P to smem as tf32 bits ----
        uint32_t* Psu = (uint32_t*)(smf + 22272);
        #pragma unroll
        for (int half = 0; half < 2; half++) {
            const int row_l = wid * 16 + g + half * 8;
            float mx = -1e30f;
            #pragma unroll
            for (int ni = 0; ni < 8; ni++) {
                #pragma unroll
                for (int c = 0; c < 2; c++) {
                    float v = sacc[ni][half * 2 + c] * 0.125f;
                    if (MODE == 0) {
                        if (kt == qt) {
                            int keyl = ni * 8 + 2 * t + c;
                            if (keyl > row_l) v = -1e30f;
                        }
                    } else {
                        v += Bic[row_l * 68 + ni * 8 + 2 * t + c];
                    }
                    sacc[ni][half * 2 + c] = v;
                    mx = fmaxf(mx, v);
                }
            }
            mx = fmaxf(mx, __shfl_xor_sync(0xffffffffu, mx, 1));
            mx = fmaxf(mx, __shfl_xor_sync(0xffffffffu, mx, 2));
            float mnew = fmaxf(mrow[half], mx);
            float corr = __expf(mrow[half] - mnew);
            mrow[half] = mnew;
            float sum = 0.0f;
            #pragma unroll
            for (int ni = 0; ni < 8; ni++) {
                float p0 = __expf(sacc[ni][half * 2]     - mnew);
                float p1 = __expf(sacc[ni][half * 2 + 1] - mnew);
                sum += p0 + p1;
                sacc[ni][half * 2]     = p0;
                sacc[ni][half * 2 + 1] = p1;
            }
            sum += __shfl_xor_sync(0xffffffffu, sum, 1);
            sum += __shfl_xor_sync(0xffffffffu, sum, 2);
            lrow[half] = lrow[half] * corr + sum;
            #pragma unroll
            for (int ni = 0; ni < 8; ni++) {
                oacc[ni][half * 2]     *= corr;
                oacc[ni][half * 2 + 1] *= corr;
                uint2 pp = make_uint2(f2tf32(sacc[ni][half * 2]),
                                      f2tf32(sacc[ni][half * 2 + 1]));
                *(uint2*)&Psu[row_l * 68 + ni * 8 + 2 * t] = pp;
            }
        }
        __syncwarp();

        // ---- O += P V ----
        {
            const uint32_t* pb = Psu + (wid * 16 + g) * 68 + t;
            const float* vb = Vsc + t * 72 + g;
            #pragma unroll
            for (int kk = 0; kk < 8; kk++) {
                uint32_t a[4];
                a[0] = pb[kk * 8];
                a[1] = pb[8 * 68 + kk * 8];
                a[2] = pb[kk * 8 + 4];
                a[3] = pb[8 * 68 + kk * 8 + 4];
                #pragma unroll
                for (int ni = 0; ni < 8; ni++) {
                    uint32_t bf[2];
                    bf[0] = f2tf32(vb[kk * 8 * 72 + ni * 8]);
                    bf[1] = f2tf32(vb[kk * 8 * 72 + 4 * 72 + ni * 8]);
                    mma_tf32(oacc[ni], a, bf);
                }
            }
        }
        __syncwarp();   // Ps reuse next iteration guarded per-warp
    }

    // ---- normalize + write O ----
    #pragma unroll
    for (int half = 0; half < 2; half++) {
        const int row_l = wid * 16 + g + half * 8;
        const int qg = qt * 64 + row_l;
        const float invl = 1.0f / lrow[half];
        float* op = O + ((size_t)(b * LT) + qg) * DD + h * HD;
        #pragma unroll
        for (int ni = 0; ni < 8; ni++) {
            float2 v = make_float2(oacc[ni][half * 2] * invl,
                                   oacc[ni][half * 2 + 1] * invl);
            *(float2*)(op + ni * 8 + 2 * t) = v;
        }
    }
}

// ---------------------------------------------------------------------------
extern "C" void kernel_launch(void* const* d_in, const int* in_sizes, int n_in,
                              void* d_out, int out_size)
{
    const float* x        = (const float*)d_in[0];
    const float* memory   = (const float*)d_in[1];
    const float* pos_emb  = (const float*)d_in[2];
    const float* gamma_sa = (const float*)d_in[4];
    const float* wq_s     = (const float*)d_in[5];
    const float* wk_s     = (const float*)d_in[6];
    const float* wv_s     = (const float*)d_in[7];
    const float* wo_s     = (const float*)d_in[8];
    const float* gamma_ca = (const float*)d_in[9];
    const float* wq_c     = (const float*)d_in[10];
    const float* wk_c     = (const float*)d_in[11];
    const float* wv_c     = (const float*)d_in[12];
    const float* wo_c     = (const float*)d_in[13];
    const float* gamma_m  = (const float*)d_in[14];
    const float* w1       = (const float*)d_in[15];
    const float* w2       = (const float*)d_in[16];

    float* scratch = nullptr;
    cudaGetSymbolAddress((void**)&scratch, g_scratch);
    float* bh    = scratch;
    float* bq    = scratch + (size_t)1 * SLOT;
    float* battn = scratch + (size_t)2 * SLOT;
    float* bx1   = scratch + (size_t)3 * SLOT;
    float* bx2   = scratch + (size_t)4 * SLOT;
    float* bffn  = scratch + (size_t)5 * SLOT;

    float* out   = (float*)d_out;
    float* o_mlp = out;
    float* o_ks  = out + (size_t)1 * SLOT;
    float* o_vs  = out + (size_t)2 * SLOT;
    float* o_kc  = out + (size_t)3 * SLOT;
    float* o_vc  = out + (size_t)4 * SLOT;

    cudaFuncSetAttribute(tc_gemm<0>, cudaFuncAttributeMaxDynamicSharedMemorySize, TC_SMEM_BYTES);
    cudaFuncSetAttribute(tc_gemm<1>, cudaFuncAttributeMaxDynamicSharedMemorySize, TC_SMEM_BYTES);
    cudaFuncSetAttribute(tc_gemm<2>, cudaFuncAttributeMaxDynamicSharedMemorySize, TC_SMEM_BYTES);
    cudaFuncSetAttribute(tc_gemm<3>, cudaFuncAttributeMaxDynamicSharedMemorySize, TC_SMEM_BYTES);
    cudaFuncSetAttribute(attn_tc<0>, cudaFuncAttributeMaxDynamicSharedMemorySize, ATT_SMEM0);
    cudaFuncSetAttribute(attn_tc<1>, cudaFuncAttributeMaxDynamicSharedMemorySize, ATT_SMEM1);

    const dim3 gD(DD / TC_BN, MTOT / TC_BM);   // (8, 32)
    const dim3 gF(FF / TC_BN, MTOT / TC_BM);   // (32, 32)
    const dim3 gA(LT / 64, HH, BB);

    // ---- self-attention block ----
    rmsnorm_kernel<<<MTOT, 256>>>(x, gamma_sa, bh);
    tc_gemm<0><<<gD, 256, TC_SMEM_BYTES>>>(bh, wq_s, bq,   nullptr, MTOT, DD, DD);
    tc_gemm<1><<<gD, 256, TC_SMEM_BYTES>>>(bh, wk_s, o_ks, nullptr, MTOT, DD, DD);
    tc_gemm<1><<<gD, 256, TC_SMEM_BYTES>>>(bh, wv_s, o_vs, nullptr, MTOT, DD, DD);
    attn_tc<0><<<gA, 128, ATT_SMEM0>>>(bq, o_ks, o_vs, nullptr, battn);
    tc_gemm<2><<<gD, 256, TC_SMEM_BYTES>>>(battn, wo_s, bx1, x, MTOT, DD, DD);

    // ---- cross-attention block ----
    rmsnorm_kernel<<<MTOT, 256>>>(bx1, gamma_ca, bh);
    tc_gemm<0><<<gD, 256, TC_SMEM_BYTES>>>(bh,     wq_c, bq,   nullptr, MTOT, DD, DD);
    tc_gemm<1><<<gD, 256, TC_SMEM_BYTES>>>(memory, wk_c, o_kc, nullptr, MTOT, DD, DD);
    tc_gemm<1><<<gD, 256, TC_SMEM_BYTES>>>(memory, wv_c, o_vc, nullptr, MTOT, DD, DD);
    attn_tc<1><<<gA, 128, ATT_SMEM1>>>(bq, o_kc, o_vc, pos_emb, battn);
    tc_gemm<2><<<gD, 256, TC_SMEM_BYTES>>>(battn, wo_c, bx2, bx1, MTOT, DD, DD);

    // ---- FFN block ----
    rmsnorm_kernel<<<MTOT, 256>>>(bx2, gamma_m, bh);
    tc_gemm<3><<<gF, 256, TC_SMEM_BYTES>>>(bh,   w1, bffn,  nullptr, MTOT, FF, DD);
    tc_gemm<2><<<gD, 256, TC_SMEM_BYTES>>>(bffn, w2, o_mlp, bx2,     MTOT, DD, FF);
}

// round 6
// speedup vs baseline: 4.0997x; 1.0416x over previous
#include <cuda_runtime.h>
#include <cuda_bf16.h>
#include <cstdint>

// Problem constants
#define BB 4
#define LT 1024
#define LS 1024
#define DD 1024
#define HH 16
#define HD 64
#define FF 4096
#define MTOT (BB*LT)   // 4096 rows

#define SLOT (MTOT*DD)                     // 4M floats
#define WSZ  (DD*DD)                       // 1M floats
// scratch: 5 act slots + ffn + rounded weights/memory
//   [0..5)*SLOT   : bh, bq, battn, bx1, bx2
//   5*SLOT        : bffn (MTOT*FF)
//   WBASE + i*WSZ : 8 rounded D x D weights
//   WBASE + 8*WSZ : w1r (4*WSZ), +12*WSZ: w2r (4*WSZ), +16*WSZ: memr (4*WSZ)
#define WBASE ((size_t)5*SLOT + (size_t)MTOT*FF)
__device__ float g_scratch[WBASE + 20*(size_t)WSZ];

// ---------------------------------------------------------------------------
__device__ __forceinline__ uint32_t f2tf32(float f) {
    uint32_t u;
    asm("cvt.rna.tf32.f32 %0, %1;" : "=r"(u) : "f"(f));
    return u;
}
__device__ __forceinline__ float rtf(float f) {   // round to tf32, as float
    return __uint_as_float(f2tf32(f));
}

__device__ __forceinline__ void mma_tf32(float* d, const uint32_t* a, const uint32_t* b) {
    asm volatile(
        "mma.sync.aligned.m16n8k8.row.col.f32.tf32.tf32.f32 "
        "{%0,%1,%2,%3}, {%4,%5,%6,%7}, {%8,%9}, {%0,%1,%2,%3};"
        : "+f"(d[0]), "+f"(d[1]), "+f"(d[2]), "+f"(d[3])
        : "r"(a[0]), "r"(a[1]), "r"(a[2]), "r"(a[3]), "r"(b[0]), "r"(b[1]));
}

__device__ __forceinline__ void cp16(uint32_t dst, const float* src) {
    asm volatile("cp.async.cg.shared.global [%0], [%1], 16;" :: "r"(dst), "l"(src));
}

// ---------------------------------------------------------------------------
// Elementwise tf32 rounding pass (float4 per thread)
__global__ void round_tf32_kernel(const float4* __restrict__ in,
                                  float4* __restrict__ out)
{
    int idx = blockIdx.x * 256 + threadIdx.x;
    float4 v = in[idx];
    v.x = rtf(v.x); v.y = rtf(v.y); v.z = rtf(v.z); v.w = rtf(v.w);
    out[idx] = v;
}

// ---------------------------------------------------------------------------
// RMSNorm (output rounded to tf32 — it only feeds GEMM A operands)
__global__ void rmsnorm_kernel(const float* __restrict__ x,
                               const float* __restrict__ g,
                               float* __restrict__ out)
{
    __shared__ float red[256];
    int row = blockIdx.x;
    int tid = threadIdx.x;
    const float4* xr = (const float4*)(x + (size_t)row * DD);
    float4 v = xr[tid];
    float ss = v.x*v.x + v.y*v.y + v.z*v.z + v.w*v.w;
    red[tid] = ss;
    __syncthreads();
    #pragma unroll
    for (int s = 128; s > 0; s >>= 1) {
        if (tid < s) red[tid] += red[tid + s];
        __syncthreads();
    }
    float inv = rsqrtf(red[0] * (1.0f/(float)DD) + 1e-6f);
    const float4 gg = ((const float4*)g)[tid];
    float4 o;
    o.x = rtf(v.x * inv * gg.x);
    o.y = rtf(v.y * inv * gg.y);
    o.z = rtf(v.z * inv * gg.z);
    o.w = rtf(v.w * inv * gg.w);
    ((float4*)(out + (size_t)row * DD))[tid] = o;
}

// ---------------------------------------------------------------------------
// TF32 tensor-core GEMM. Operands MUST be pre-rounded to tf32 (raw-bit loads).
// Epilogues: 1 KV-transpose, 2 resid, 3 relu+round, 4 plain+round.
#define TC_BM 128
#define TC_BN 128
#define TC_BK 32
#define AS_STRIDE (TC_BK + 8)
#define BS_STRIDE (TC_BN + 8)
#define AS_ELEMS (TC_BM * AS_STRIDE)
#define BS_ELEMS (TC_BK * BS_STRIDE)
#define TC_SMEM_BYTES (2 * (AS_ELEMS + BS_ELEMS) * 4)

template<int EPI>
__global__ __launch_bounds__(256)
void tc_gemm(const float* __restrict__ A, const float* __restrict__ B,
             float* __restrict__ C, const float* __restrict__ R,
             int M, int N, int K)
{
    extern __shared__ float sm[];
    float* As0 = sm;
    float* As1 = sm + AS_ELEMS;
    float* Bs0 = sm + 2 * AS_ELEMS;
    float* Bs1 = sm + 2 * AS_ELEMS + BS_ELEMS;

    const int tid  = threadIdx.x;
    const int wid  = tid >> 5;
    const int lane = tid & 31;
    const int g    = lane >> 2;
    const int t    = lane & 3;
    const int wm   = wid & 1;
    const int wn   = wid >> 1;
    const int m0   = blockIdx.y * TC_BM;
    const int n0   = blockIdx.x * TC_BN;

    const int a_m = tid >> 3;
    const int a_c = (tid & 7) * 4;
    const int b_k = tid >> 5;
    const int b_c = (tid & 31) * 4;

    const uint32_t asm0 = (uint32_t)__cvta_generic_to_shared(As0);
    const uint32_t asm1 = (uint32_t)__cvta_generic_to_shared(As1);
    const uint32_t bsm0 = (uint32_t)__cvta_generic_to_shared(Bs0);
    const uint32_t bsm1 = (uint32_t)__cvta_generic_to_shared(Bs1);

    float acc[4][4][4];
    #pragma unroll
    for (int mi = 0; mi < 4; mi++)
        #pragma unroll
        for (int ni = 0; ni < 4; ni++)
            #pragma unroll
            for (int r = 0; r < 4; r++) acc[mi][ni][r] = 0.0f;

    const int NT = K / TC_BK;

    {
        #pragma unroll
        for (int p = 0; p < 4; p++) {
            int r = a_m + p * 32;
            cp16(asm0 + (uint32_t)((r * AS_STRIDE + a_c) << 2),
                 A + (size_t)(m0 + r) * K + a_c);
        }
        #pragma unroll
        for (int p = 0; p < 4; p++) {
            int r = b_k + p * 8;
            cp16(bsm0 + (uint32_t)((r * BS_STRIDE + b_c) << 2),
                 B + (size_t)r * N + n0 + b_c);
        }
        asm volatile("cp.async.commit_group;");
    }

    for (int kt = 0; kt < NT; kt++) {
        const int cur = kt & 1;
        if (kt + 1 < NT) {
            const int k0 = (kt + 1) * TC_BK;
            uint32_t ad = cur ? asm0 : asm1;
            uint32_t bd = cur ? bsm0 : bsm1;
            #pragma unroll
            for (int p = 0; p < 4; p++) {
                int r = a_m + p * 32;
                cp16(ad + (uint32_t)((r * AS_STRIDE + a_c) << 2),
                     A + (size_t)(m0 + r) * K + k0 + a_c);
            }
            #pragma unroll
            for (int p = 0; p < 4; p++) {
                int r = b_k + p * 8;
                cp16(bd + (uint32_t)((r * BS_STRIDE + b_c) << 2),
                     B + (size_t)(k0 + r) * N + n0 + b_c);
            }
            asm volatile("cp.async.commit_group;");
            asm volatile("cp.async.wait_group 1;");
        } else {
            asm volatile("cp.async.wait_group 0;");
        }
        __syncthreads();

        const uint32_t* Ab = (const uint32_t*)((cur ? As1 : As0) + (wm * 64 + g) * AS_STRIDE + t);
        const uint32_t* Bb = (const uint32_t*)((cur ? Bs1 : Bs0) + t * BS_STRIDE + wn * 32 + g);

        #pragma unroll
        for (int kk = 0; kk < 4; kk++) {
            uint32_t af[4][4];
            uint32_t bf[4][2];
            #pragma unroll
            for (int mi = 0; mi < 4; mi++) {
                const uint32_t* p = Ab + mi * 16 * AS_STRIDE + kk * 8;
                af[mi][0] = p[0];
                af[mi][1] = p[8 * AS_STRIDE];
                af[mi][2] = p[4];
                af[mi][3] = p[8 * AS_STRIDE + 4];
            }
            #pragma unroll
            for (int ni = 0; ni < 4; ni++) {
                const uint32_t* p = Bb + kk * 8 * BS_STRIDE + ni * 8;
                bf[ni][0] = p[0];
                bf[ni][1] = p[4 * BS_STRIDE];
            }
            #pragma unroll
            for (int mi = 0; mi < 4; mi++)
                #pragma unroll
                for (int ni = 0; ni < 4; ni++)
                    mma_tf32(acc[mi][ni], af[mi], bf[ni]);
        }
        __syncthreads();
    }

    const int mbase = m0 + wm * 64 + g;
    const int nbase = n0 + wn * 32 + 2 * t;

    if (EPI == 1) {
        #pragma unroll
        for (int mi = 0; mi < 4; mi++) {
            #pragma unroll
            for (int ni = 0; ni < 4; ni++) {
                #pragma unroll
                for (int half = 0; half < 2; half++) {
                    int m = mbase + mi * 16 + half * 8;
                    int b = m >> 10, l = m & 1023;
                    #pragma unroll
                    for (int c = 0; c < 2; c++) {
                        int n = nbase + ni * 8 + c;
                        int h = n >> 6, d = n & 63;
                        C[(((size_t)(b * HH + h) * LT + l) << 6) + d] =
                            acc[mi][ni][half * 2 + c];
                    }
                }
            }
        }
    } else {
        #pragma unroll
        for (int mi = 0; mi < 4; mi++) {
            #pragma unroll
            for (int ni = 0; ni < 4; ni++) {
                int n = nbase + ni * 8;
                #pragma unroll
                for (int half = 0; half < 2; half++) {
                    int m = mbase + mi * 16 + half * 8;
                    size_t off = (size_t)m * N + n;
                    float2 v = make_float2(acc[mi][ni][half * 2], acc[mi][ni][half * 2 + 1]);
                    if (EPI == 2) {
                        float2 r = *(const float2*)(R + off);
                        v.x += r.x; v.y += r.y;
                    }
                    if (EPI == 3) {
                        v.x = rtf(fmaxf(v.x, 0.f)); v.y = rtf(fmaxf(v.y, 0.f));
                    }
                    if (EPI == 4) {
                        v.x = rtf(v.x); v.y = rtf(v.y);
                    }
                    *(float2*)(C + off) = v;
                }
            }
        }
    }
}

// ---------------------------------------------------------------------------
// Tensor-core flash attention (tf32 mma, online softmax).
// Q pre-rounded to tf32 (raw loads); K/V kept exact fp32 (cvt at frag load).
#define ATT_SMEM0 (26624 * 4)
#define ATT_SMEM1 (35328 * 4)

#define LOAD_TILE(dstoff, srcptr, srcstride, STRIDE)                          \
    _Pragma("unroll")                                                         \
    for (int i_ = 0; i_ < 8; i_++) {                                          \
        int idx_ = tid + i_ * 128;                                            \
        int r_ = idx_ >> 4, c_ = (idx_ & 15) * 4;                             \
        cp16(sbase + (uint32_t)(((dstoff) + r_ * (STRIDE) + c_) << 2),        \
             (srcptr) + (size_t)r_ * (srcstride) + c_);                       \
    }

template<int MODE>
__global__ __launch_bounds__(128)
void attn_tc(const float* __restrict__ Q, const float* __restrict__ K,
             const float* __restrict__ V, const float* __restrict__ bias,
             float* __restrict__ O)
{
    extern __shared__ float smf[];
    const int tid  = threadIdx.x;
    const int wid  = tid >> 5;
    const int lane = tid & 31;
    const int g    = lane >> 2;
    const int t    = lane & 3;
    const int qt   = blockIdx.x;
    const int h    = blockIdx.y;
    const int b    = blockIdx.z;

    const uint32_t sbase = (uint32_t)__cvta_generic_to_shared(smf);

    const float* Qg = Q + ((size_t)(b * LT) + qt * 64) * DD + h * HD;
    const float* Kg = K + ((size_t)(b * HH + h)) * LS * HD;
    const float* Vg = V + ((size_t)(b * HH + h)) * LS * HD;
    const float* Bg = (MODE == 1) ? bias + ((size_t)h * LT + qt * 64) * LS : nullptr;

    {
        LOAD_TILE(0,     Qg, DD, 68);
        LOAD_TILE(4352,  Kg, HD, 68);
        LOAD_TILE(13056, Vg, HD, 72);
        if (MODE == 1) {
            LOAD_TILE(26624, Bg, LS, 68);
        }
        asm volatile("cp.async.commit_group;");
    }

    float oacc[8][4];
    #pragma unroll
    for (int ni = 0; ni < 8; ni++)
        #pragma unroll
        for (int r = 0; r < 4; r++) oacc[ni][r] = 0.0f;

    float mrow[2] = { -1e30f, -1e30f };
    float lrow[2] = { 0.0f, 0.0f };

    const int ktmax = (MODE == 0) ? qt : (LS / 64 - 1);

    for (int kt = 0; kt <= ktmax; kt++) {
        const int cur = kt & 1;
        __syncthreads();
        if (kt + 1 <= ktmax) {
            const int nk = kt + 1;
            const uint32_t koff = (cur == 0) ? 8704u  : 4352u;
            const uint32_t voff = (cur == 0) ? 17664u : 13056u;
            const float* kp = Kg + (size_t)nk * 64 * HD;
            const float* vp = Vg + (size_t)nk * 64 * HD;
            LOAD_TILE(koff, kp, HD, 68);
            LOAD_TILE(voff, vp, HD, 72);
            if (MODE == 1) {
                const uint32_t boff = (cur == 0) ? 30976u : 26624u;
                const float* bp = Bg + (size_t)nk * 64;
                LOAD_TILE(boff, bp, LS, 68);
            }
            asm volatile("cp.async.commit_group;");
            asm volatile("cp.async.wait_group 1;");
        } else {
            asm volatile("cp.async.wait_group 0;");
        }
        __syncthreads();

        const float* Ksc = smf + (cur ? 8704 : 4352);
        const float* Vsc = smf + (cur ? 17664 : 13056);
        const float* Bic = smf + (cur ? 30976 : 26624);

        // ---- S = Q K^T ----
        float sacc[8][4];
        #pragma unroll
        for (int ni = 0; ni < 8; ni++)
            #pragma unroll
            for (int r = 0; r < 4; r++) sacc[ni][r] = 0.0f;

        {
            const uint32_t* qb = (const uint32_t*)(smf + (wid * 16 + g) * 68 + t);
            const float* kb = Ksc + g * 68 + t;
            #pragma unroll
            for (int kk = 0; kk < 8; kk++) {
                uint32_t a[4];
                a[0] = qb[kk * 8];
                a[1] = qb[8 * 68 + kk * 8];
                a[2] = qb[kk * 8 + 4];
                a[3] = qb[8 * 68 + kk * 8 + 4];
                #pragma unroll
                for (int ni = 0; ni < 8; ni++) {
                    uint32_t bf[2];
                    bf[0] = f2tf32(kb[ni * 8 * 68 + kk * 8]);
                    bf[1] = f2tf32(kb[ni * 8 * 68 + kk * 8 + 4]);
                    mma_tf32(sacc[ni], a, bf);
                }
            }
        }

        // ---- softmax ----
        uint32_t* Psu = (uint32_t*)(smf + 22272);
        #pragma unroll
        for (int half = 0; half < 2; half++) {
            const int row_l = wid * 16 + g + half * 8;
            float mx = -1e30f;
            #pragma unroll
            for (int ni = 0; ni < 8; ni++) {
                #pragma unroll
                for (int c = 0; c < 2; c++) {
                    float v = sacc[ni][half * 2 + c] * 0.125f;
                    if (MODE == 0) {
                        if (kt == qt) {
                            int keyl = ni * 8 + 2 * t + c;
                            if (keyl > row_l) v = -1e30f;
                        }
                    } else {
                        v += Bic[row_l * 68 + ni * 8 + 2 * t + c];
                    }
                    sacc[ni][half * 2 + c] = v;
                    mx = fmaxf(mx, v);
                }
            }
            mx = fmaxf(mx, __shfl_xor_sync(0xffffffffu, mx, 1));
            mx = fmaxf(mx, __shfl_xor_sync(0xffffffffu, mx, 2));
            float mnew = fmaxf(mrow[half], mx);
            float corr = __expf(mrow[half] - mnew);
            mrow[half] = mnew;
            float sum = 0.0f;
            #pragma unroll
            for (int ni = 0; ni < 8; ni++) {
                float p0 = __expf(sacc[ni][half * 2]     - mnew);
                float p1 = __expf(sacc[ni][half * 2 + 1] - mnew);
                sum += p0 + p1;
                sacc[ni][half * 2]     = p0;
                sacc[ni][half * 2 + 1] = p1;
            }
            sum += __shfl_xor_sync(0xffffffffu, sum, 1);
            sum += __shfl_xor_sync(0xffffffffu, sum, 2);
            lrow[half] = lrow[half] * corr + sum;
            #pragma unroll
            for (int ni = 0; ni < 8; ni++) {
                oacc[ni][half * 2]     *= corr;
                oacc[ni][half * 2 + 1] *= corr;
                uint2 pp = make_uint2(f2tf32(sacc[ni][half * 2]),
                                      f2tf32(sacc[ni][half * 2 + 1]));
                *(uint2*)&Psu[row_l * 68 + ni * 8 + 2 * t] = pp;
            }
        }
        __syncwarp();

        // ---- O += P V ----
        {
            const uint32_t* pb = Psu + (wid * 16 + g) * 68 + t;
            const float* vb = Vsc + t * 72 + g;
            #pragma unroll
            for (int kk = 0; kk < 8; kk++) {
                uint32_t a[4];
                a[0] = pb[kk * 8];
                a[1] = pb[8 * 68 + kk * 8];
                a[2] = pb[kk * 8 + 4];
                a[3] = pb[8 * 68 + kk * 8 + 4];
                #pragma unroll
                for (int ni = 0; ni < 8; ni++) {
                    uint32_t bf[2];
                    bf[0] = f2tf32(vb[kk * 8 * 72 + ni * 8]);
                    bf[1] = f2tf32(vb[kk * 8 * 72 + 4 * 72 + ni * 8]);
                    mma_tf32(oacc[ni], a, bf);
                }
            }
        }
        __syncwarp();
    }

    // ---- normalize + write O (rounded: feeds GEMM A) ----
    #pragma unroll
    for (int half = 0; half < 2; half++) {
        const int row_l = wid * 16 + g + half * 8;
        const int qg = qt * 64 + row_l;
        const float invl = 1.0f / lrow[half];
        float* op = O + ((size_t)(b * LT) + qg) * DD + h * HD;
        #pragma unroll
        for (int ni = 0; ni < 8; ni++) {
            float2 v = make_float2(rtf(oacc[ni][half * 2] * invl),
                                   rtf(oacc[ni][half * 2 + 1] * invl));
            *(float2*)(op + ni * 8 + 2 * t) = v;
        }
    }
}

// ---------------------------------------------------------------------------
extern "C" void kernel_launch(void* const* d_in, const int* in_sizes, int n_in,
                              void* d_out, int out_size)
{
    const float* x        = (const float*)d_in[0];
    const float* memory   = (const float*)d_in[1];
    const float* pos_emb  = (const float*)d_in[2];
    const float* gamma_sa = (const float*)d_in[4];
    const float* wq_s     = (const float*)d_in[5];
    const float* wk_s     = (const float*)d_in[6];
    const float* wv_s     = (const float*)d_in[7];
    const float* wo_s     = (const float*)d_in[8];
    const float* gamma_ca = (const float*)d_in[9];
    const float* wq_c     = (const float*)d_in[10];
    const float* wk_c     = (const float*)d_in[11];
    const float* wv_c     = (const float*)d_in[12];
    const float* wo_c     = (const float*)d_in[13];
    const float* gamma_m  = (const float*)d_in[14];
    const float* w1       = (const float*)d_in[15];
    const float* w2       = (const float*)d_in[16];

    float* scratch = nullptr;
    cudaGetSymbolAddress((void**)&scratch, g_scratch);
    float* bh    = scratch;
    float* bq    = scratch + (size_t)1 * SLOT;
    float* battn = scratch + (size_t)2 * SLOT;
    float* bx1   = scratch + (size_t)3 * SLOT;
    float* bx2   = scratch + (size_t)4 * SLOT;
    float* bffn  = scratch + (size_t)5 * SLOT;
    float* wbase = scratch + WBASE;
    float* rwq_s = wbase + 0 * (size_t)WSZ;
    float* rwk_s = wbase + 1 * (size_t)WSZ;
    float* rwv_s = wbase + 2 * (size_t)WSZ;
    float* rwo_s = wbase + 3 * (size_t)WSZ;
    float* rwq_c = wbase + 4 * (size_t)WSZ;
    float* rwk_c = wbase + 5 * (size_t)WSZ;
    float* rwv_c = wbase + 6 * (size_t)WSZ;
    float* rwo_c = wbase + 7 * (size_t)WSZ;
    float* rw1   = wbase + 8 * (size_t)WSZ;    // 4*WSZ
    float* rw2   = wbase + 12 * (size_t)WSZ;   // 4*WSZ
    float* rmem  = wbase + 16 * (size_t)WSZ;   // 4*WSZ

    float* out   = (float*)d_out;
    float* o_mlp = out;
    float* o_ks  = out + (size_t)1 * SLOT;
    float* o_vs  = out + (size_t)2 * SLOT;
    float* o_kc  = out + (size_t)3 * SLOT;
    float* o_vc  = out + (size_t)4 * SLOT;

    cudaFuncSetAttribute(tc_gemm<1>, cudaFuncAttributeMaxDynamicSharedMemorySize, TC_SMEM_BYTES);
    cudaFuncSetAttribute(tc_gemm<2>, cudaFuncAttributeMaxDynamicSharedMemorySize, TC_SMEM_BYTES);
    cudaFuncSetAttribute(tc_gemm<3>, cudaFuncAttributeMaxDynamicSharedMemorySize, TC_SMEM_BYTES);
    cudaFuncSetAttribute(tc_gemm<4>, cudaFuncAttributeMaxDynamicSharedMemorySize, TC_SMEM_BYTES);
    cudaFuncSetAttribute(attn_tc<0>, cudaFuncAttributeMaxDynamicSharedMemorySize, ATT_SMEM0);
    cudaFuncSetAttribute(attn_tc<1>, cudaFuncAttributeMaxDynamicSharedMemorySize, ATT_SMEM1);

    // ---- tf32 rounding passes (weights + memory) ----
    #define RND(src, dst, nfloats) \
        round_tf32_kernel<<<(nfloats)/4/256, 256>>>((const float4*)(src), (float4*)(dst))
    RND(wq_s, rwq_s, WSZ); RND(wk_s, rwk_s, WSZ);
    RND(wv_s, rwv_s, WSZ); RND(wo_s, rwo_s, WSZ);
    RND(wq_c, rwq_c, WSZ); RND(wk_c, rwk_c, WSZ);
    RND(wv_c, rwv_c, WSZ); RND(wo_c, rwo_c, WSZ);
    RND(w1, rw1, 4*WSZ);   RND(w2, rw2, 4*WSZ);
    RND(memory, rmem, 4*WSZ);
    #undef RND

    const dim3 gD(DD / TC_BN, MTOT / TC_BM);   // (8, 32)
    const dim3 gF(FF / TC_BN, MTOT / TC_BM);   // (32, 32)
    const dim3 gA(LT / 64, HH, BB);

    // ---- self-attention block ----
    rmsnorm_kernel<<<MTOT, 256>>>(x, gamma_sa, bh);
    tc_gemm<4><<<gD, 256, TC_SMEM_BYTES>>>(bh, rwq_s, bq,   nullptr, MTOT, DD, DD);
    tc_gemm<1><<<gD, 256, TC_SMEM_BYTES>>>(bh, rwk_s, o_ks, nullptr, MTOT, DD, DD);
    tc_gemm<1><<<gD, 256, TC_SMEM_BYTES>>>(bh, rwv_s, o_vs, nullptr, MTOT, DD, DD);
    attn_tc<0><<<gA, 128, ATT_SMEM0>>>(bq, o_ks, o_vs, nullptr, battn);
    tc_gemm<2><<<gD, 256, TC_SMEM_BYTES>>>(battn, rwo_s, bx1, x, MTOT, DD, DD);

    // ---- cross-attention block ----
    rmsnorm_kernel<<<MTOT, 256>>>(bx1, gamma_ca, bh);
    tc_gemm<4><<<gD, 256, TC_SMEM_BYTES>>>(bh,   rwq_c, bq,   nullptr, MTOT, DD, DD);
    tc_gemm<1><<<gD, 256, TC_SMEM_BYTES>>>(rmem, rwk_c, o_kc, nullptr, MTOT, DD, DD);
    tc_gemm<1><<<gD, 256, TC_SMEM_BYTES>>>(rmem, rwv_c, o_vc, nullptr, MTOT, DD, DD);
    attn_tc<1><<<gA, 128, ATT_SMEM1>>>(bq, o_kc, o_vc, pos_emb, battn);
    tc_gemm<2><<<gD, 256, TC_SMEM_BYTES>>>(battn, rwo_c, bx2, bx1, MTOT, DD, DD);

    // ---- FFN block ----
    rmsnorm_kernel<<<MTOT, 256>>>(bx2, gamma_m, bh);
    tc_gemm<3><<<gF, 256, TC_SMEM_BYTES>>>(bh,   rw1, bffn,  nullptr, MTOT, FF, DD);
    tc_gemm<2><<<gD, 256, TC_SMEM_BYTES>>>(bffn, rw2, o_mlp, bx2,     MTOT, DD, FF);
}